// round 13
// baseline (speedup 1.0000x reference)
#include <cuda_runtime.h>
#include <cuda_bf16.h>
#include <cstdint>

// Shapes fixed by setup_inputs: L=4, B=8, C=256, H=64, W=64
#define L_DIM 4
#define B_DIM 8
#define C_DIM 256
#define SPATIAL 4096
#define S4 (SPATIAL / 4)                 // 1024 float4 per slab
#define SLABS_PER_B (L_DIM * C_DIM)      // 1024 slabs per batch
#define PAIRS_PER_B (SLABS_PER_B / 2)    // 512 pair-tickets per batch
#define BPG 74                           // blocks per batch-group
#define GRID_X (B_DIM * BPG)             // 592 = 148 SMs * 4 blocks, one wave
#define NTHR 256
#define INV_SPATIAL (1.0f / 4096.0f)

// Cross-block state (allocation-free rule -> __device__ globals, zero-init).
__device__ float    g_gap [B_DIM][SLABS_PER_B];
__device__ float    g_attn[B_DIM][SLABS_PER_B];
__device__ unsigned g_t1[B_DIM];         // phase-1 pair tickets
__device__ unsigned g_t3[B_DIM];         // phase-3 slab tickets
__device__ unsigned g_gap_done[B_DIM];
__device__ unsigned g_attn_done[B_DIM];
__device__ unsigned g_exit_count;

__global__ __launch_bounds__(NTHR, 4) void sffm_fused(const float* __restrict__ in,
                                                      const float* __restrict__ Wm,
                                                      float* __restrict__ out) {
    const int bid  = blockIdx.x;
    const int b    = bid / BPG;          // batch group — all 8 concurrent
    const int j    = bid - b * BPG;      // block within group (phase-2 static)
    const int t    = threadIdx.x;
    const int lane = t & 31;
    const int warp = t >> 5;

    __shared__ float    gap_sm[L_DIM * C_DIM];  // 4 KB staged gap
    __shared__ float    ws[2][8];
    __shared__ unsigned sm_tk;

    const float4* in4  = (const float4*)in;
    float4*       out4 = (float4*)out;

    // ========= Phase 1: GAP, pair-stealing with PIPELINED ticket =========
    // Same load/reduce pattern + sync count as the proven R6 loop; the next
    // ticket's atomic is issued under the current pair's loads, so stealing
    // adds no stalls — it only equalizes block finish times at the barrier.
    if (t == 0) sm_tk = atomicAdd(&g_t1[b], 1u);
    __syncthreads();
    unsigned tk = sm_tk;
    for (;;) {
        if (tk >= PAIRS_PER_B) break;
        const int s0 = 2 * (int)tk, s1 = s0 + 1;     // contiguous 32 KB
        const int l0 = s0 >> 8, c0 = s0 & 255;
        const size_t base0 = ((size_t)((l0 * B_DIM + b) * C_DIM + c0)) * S4;
        const size_t base1 = base0 + S4;
        float4 v0[4], v1[4];
#pragma unroll
        for (int i = 0; i < 4; i++) v0[i] = in4[base0 + t + i * 256];
#pragma unroll
        for (int i = 0; i < 4; i++) v1[i] = in4[base1 + t + i * 256];
        if (t == 0) sm_tk = atomicAdd(&g_t1[b], 1u); // prefetch next ticket
        float r0 = 0.f, r1 = 0.f;
#pragma unroll
        for (int i = 0; i < 4; i++) {
            r0 += (v0[i].x + v0[i].y) + (v0[i].z + v0[i].w);
            r1 += (v1[i].x + v1[i].y) + (v1[i].z + v1[i].w);
        }
#pragma unroll
        for (int o = 16; o; o >>= 1) {
            r0 += __shfl_xor_sync(0xffffffffu, r0, o);
            r1 += __shfl_xor_sync(0xffffffffu, r1, o);
        }
        if (lane == 0) { ws[0][warp] = r0; ws[1][warp] = r1; }
        __syncthreads();                  // publishes ws AND sm_tk
        unsigned next = sm_tk;
        if (t == 0) {
            float a0 = 0.f, a1 = 0.f;
#pragma unroll
            for (int w = 0; w < 8; w++) { a0 += ws[0][w]; a1 += ws[1][w]; }
            g_gap[b][s0] = a0 * INV_SPATIAL;
            g_gap[b][s1] = a1 * INV_SPATIAL;
        }
        __syncthreads();                  // protect ws/sm_tk reuse
        tk = next;
    }
    if (t == 0) { __threadfence(); atomicAdd(&g_gap_done[b], 1u); }

    // ---- barrier 1: this batch's GAP table complete ----
    if (t == 0) {
        while (*(volatile unsigned*)&g_gap_done[b] < BPG) __nanosleep(64);
        __threadfence();
    }
    __syncthreads();

    // stage gap table (4 KB, L2-hot)
#pragma unroll
    for (int i = 0; i < 4; i++) gap_sm[t + i * NTHR] = g_gap[b][t + i * NTHR];
    __syncthreads();

    // ========= Phase 2: attn table, static ownership (balanced, ~1 us) =========
    {
        int nslab = 0;
        for (int s = j; s < SLABS_PER_B; s += BPG) nslab++;   // 13 or 14
        for (int k = warp; k < nslab; k += 8) {
            int s = j + k * BPG;
            int lsel = s >> 8, q = s & 255;
            const float4* wr = (const float4*)(Wm + (size_t)q * C_DIM);
            const float4* g4 = (const float4*)gap_sm;
            float sc0 = 0.f, sc1 = 0.f, sc2 = 0.f, sc3 = 0.f;
#pragma unroll
            for (int ii = 0; ii < 2; ii++) {
                int i = lane + ii * 32;
                float4 wv = wr[i];
                float4 a0 = g4[0 * 64 + i];
                float4 a1 = g4[1 * 64 + i];
                float4 a2 = g4[2 * 64 + i];
                float4 a3 = g4[3 * 64 + i];
                sc0 += wv.x * a0.x + wv.y * a0.y + wv.z * a0.z + wv.w * a0.w;
                sc1 += wv.x * a1.x + wv.y * a1.y + wv.z * a1.z + wv.w * a1.w;
                sc2 += wv.x * a2.x + wv.y * a2.y + wv.z * a2.z + wv.w * a2.w;
                sc3 += wv.x * a3.x + wv.y * a3.y + wv.z * a3.z + wv.w * a3.w;
            }
#pragma unroll
            for (int o = 16; o; o >>= 1) {
                sc0 += __shfl_xor_sync(0xffffffffu, sc0, o);
                sc1 += __shfl_xor_sync(0xffffffffu, sc1, o);
                sc2 += __shfl_xor_sync(0xffffffffu, sc2, o);
                sc3 += __shfl_xor_sync(0xffffffffu, sc3, o);
            }
            if (lane == 0) {
                float m  = fmaxf(fmaxf(sc0, sc1), fmaxf(sc2, sc3));
                float e0 = __expf(sc0 - m), e1 = __expf(sc1 - m);
                float e2 = __expf(sc2 - m), e3 = __expf(sc3 - m);
                float inv = 1.0f / (e0 + e1 + e2 + e3);
                float sel = (lsel == 0) ? e0 : (lsel == 1) ? e1
                          : (lsel == 2) ? e2 : e3;
                g_attn[b][s] = sel * inv;
            }
        }
    }
    if (t == 0) { __threadfence(); atomicAdd(&g_attn_done[b], 1u); }

    // ---- barrier 2: attn table complete (phase 2 balanced -> cheap) ----
    if (t == 0) {
        while (*(volatile unsigned*)&g_attn_done[b] < BPG) __nanosleep(64);
        __threadfence();
    }
    __syncthreads();

    // ===== Phase 3: scale via WARP-level slab stealing (no block syncs) =====
    // Ticket prefetched one slab ahead; output identical regardless of which
    // warp scales which slab (deterministic). Re-read is L2-hot (just GAPped).
    {
        unsigned s;
        if (lane == 0) s = atomicAdd(&g_t3[b], 1u);
        s = __shfl_sync(0xffffffffu, s, 0);
        while (s < SLABS_PER_B) {
            unsigned s2;
            if (lane == 0) s2 = atomicAdd(&g_t3[b], 1u);  // prefetch (hidden)
            float a = __ldg(&g_attn[b][s]);
            int l = (int)s >> 8, c = (int)s & 255;
            size_t base = ((size_t)((l * B_DIM + b) * C_DIM + c)) * S4;
#pragma unroll 8
            for (int i = 0; i < 32; i++) {
                float4 v = __ldcs(in4 + base + lane + i * 32);
                v.x *= a; v.y *= a; v.z *= a; v.w *= a;
                __stcs(out4 + base + lane + i * 32, v);
            }
            s = __shfl_sync(0xffffffffu, s2, 0);
        }
    }

    // ---- reset cross-launch state (last block out; graph-replay safe) ----
    __syncthreads();
    if (t == 0) {
        __threadfence();
        unsigned v = atomicAdd(&g_exit_count, 1u);
        if (v == GRID_X - 1) {
#pragma unroll
            for (int i = 0; i < B_DIM; i++) {
                g_t1[i] = 0; g_t3[i] = 0;
                g_gap_done[i] = 0; g_attn_done[i] = 0;
            }
            __threadfence();
            g_exit_count = 0;
        }
    }
}

extern "C" void kernel_launch(void* const* d_in, const int* in_sizes, int n_in,
                              void* d_out, int out_size) {
    const float* in  = (const float*)d_in[0];   // [L,B,C,H,W]
    const float* Wm  = (const float*)d_in[1];   // [C,C]
    float*       out = (float*)d_out;           // [L,B,C,H,W]

    sffm_fused<<<GRID_X, NTHR>>>(in, Wm, out);
}